// round 4
// baseline (speedup 1.0000x reference)
#include <cuda_runtime.h>

// AntiAliasInterpolation2d: depthwise 13x13 Gaussian, stride 4, zero pad 6.
// Input [32,3,512,512] f32, weight [3,1,13,13] f32, output [32,3,128,128] f32.
//
// Separable: 2D kernel = outer(g,g), g[j] = k2[6][j]/sqrt(k2[6][6]) (exact),
// g symmetric -> 7 distinct taps.
// Fused: horizontal filter+stride4 -> smem tile h[41][128], then vertical.
// R4: each warp processes TWO rows per iteration (independent load chains,
// ~8 LDG.128 in flight) to hide DRAM latency; 5 CTAs/SM.

#define TH   8                   // output rows per CTA
#define RR   (4 * TH + 9)        // 41 input rows needed
#define IW   512
#define IW4  128                 // input row in float4
#define OW   128
#define OW4  32                  // output row in float4

__global__ __launch_bounds__(256, 5)
void aa_interp_kernel(const float* __restrict__ inp,
                      const float* __restrict__ w,
                      float* __restrict__ out)
{
    __shared__ float  sw[8];
    __shared__ float4 h[RR][OW4];       // 41*32*16 = 20992 B

    const int nc   = blockIdx.x;        // n*3 + c
    const int c    = nc % 3;
    const int oy0  = blockIdx.y * TH;
    const int tid  = threadIdx.x;
    const int lane = tid & 31;
    const int wid  = tid >> 5;

    // Exact 1D factor from the 2D weight: gn[j] = k2[6][j] / sqrt(k2[6][6]).
    if (tid < 7) {
        sw[tid] = w[c * 169 + 78 + tid] / sqrtf(w[c * 169 + 84]);
    }
    __syncthreads();

    float g[7];
#pragma unroll
    for (int k = 0; k < 7; k++) g[k] = sw[k];

    const float4* in4 = reinterpret_cast<const float4*>(inp)
                      + (size_t)nc * (IW * IW4);
    const int rbase = oy0 * 4 - 6;
    const float4 z4 = make_float4(0.f, 0.f, 0.f, 0.f);

    // ---- horizontal pass: warp handles rows (wid+base) and (wid+base+8) ----
#pragma unroll
    for (int base = 0; base < 48; base += 16) {
        const int r1 = base + wid;            // always < RR (max 39)
        const int r2 = r1 + 8;                // may be >= RR (only r2==40 valid at base=32)
        const int iy1 = rbase + r1;
        const int iy2 = rbase + r2;
        const bool ok1 = (iy1 >= 0) && (iy1 < IW);
        const bool ok2 = (r2 < RR) && (iy2 >= 0) && (iy2 < IW);

        const float4* rowA = in4 + (size_t)max(0, min(iy1, IW - 1)) * IW4;
        const float4* rowB = in4 + (size_t)max(0, min(iy2, IW - 1)) * IW4;
        float* h1 = reinterpret_cast<float*>(&h[r1][0]);
        float* h2 = reinterpret_cast<float*>(&h[min(r2, RR - 1)][0]);

#pragma unroll
        for (int j = 0; j < 4; j++) {
            const int ox = lane + 32 * j;
            // two independent load chains -> high MLP
            float4 a0 = (ox >= 2)       ? rowA[ox - 2] : z4;
            float4 a1 = (ox >= 1)       ? rowA[ox - 1] : z4;
            float4 a2 =                   rowA[ox];
            float4 a3 = (ox <= IW4 - 2) ? rowA[ox + 1] : z4;
            float4 b0 = (ox >= 2)       ? rowB[ox - 2] : z4;
            float4 b1 = (ox >= 1)       ? rowB[ox - 1] : z4;
            float4 b2 =                   rowB[ox];
            float4 b3 = (ox <= IW4 - 2) ? rowB[ox + 1] : z4;

            // taps k=0..12 map to (block, comp); g[k]==g[12-k]
            float accA =      g[0] * a0.z;
            accA = fmaf(g[1], a0.w, accA);
            accA = fmaf(g[2], a1.x, accA);
            accA = fmaf(g[3], a1.y, accA);
            accA = fmaf(g[4], a1.z, accA);
            accA = fmaf(g[5], a1.w, accA);
            accA = fmaf(g[6], a2.x, accA);
            accA = fmaf(g[5], a2.y, accA);
            accA = fmaf(g[4], a2.z, accA);
            accA = fmaf(g[3], a2.w, accA);
            accA = fmaf(g[2], a3.x, accA);
            accA = fmaf(g[1], a3.y, accA);
            accA = fmaf(g[0], a3.z, accA);

            float accB =      g[0] * b0.z;
            accB = fmaf(g[1], b0.w, accB);
            accB = fmaf(g[2], b1.x, accB);
            accB = fmaf(g[3], b1.y, accB);
            accB = fmaf(g[4], b1.z, accB);
            accB = fmaf(g[5], b1.w, accB);
            accB = fmaf(g[6], b2.x, accB);
            accB = fmaf(g[5], b2.y, accB);
            accB = fmaf(g[4], b2.z, accB);
            accB = fmaf(g[3], b2.w, accB);
            accB = fmaf(g[2], b3.x, accB);
            accB = fmaf(g[1], b3.y, accB);
            accB = fmaf(g[0], b3.z, accB);

            h1[ox] = ok1 ? accA : 0.f;
            if (r2 < RR) h2[ox] = ok2 ? accB : 0.f;
        }
    }
    __syncthreads();

    // ---- vertical pass: warp = output row, lane = float4 column ----
    {
        const int oyl = wid;
        float4 acc;
        {
            float4 v = h[4 * oyl + 6][lane];
            acc.x = g[6] * v.x; acc.y = g[6] * v.y;
            acc.z = g[6] * v.z; acc.w = g[6] * v.w;
        }
#pragma unroll
        for (int k = 0; k < 6; k++) {
            float4 a = h[4 * oyl + k][lane];
            float4 b = h[4 * oyl + 12 - k][lane];
            acc.x = fmaf(g[k], a.x + b.x, acc.x);
            acc.y = fmaf(g[k], a.y + b.y, acc.y);
            acc.z = fmaf(g[k], a.z + b.z, acc.z);
            acc.w = fmaf(g[k], a.w + b.w, acc.w);
        }
        float4* op = reinterpret_cast<float4*>(out + (size_t)nc * (OW * OW)
                                                   + (size_t)(oy0 + oyl) * OW);
        op[lane] = acc;
    }
}

extern "C" void kernel_launch(void* const* d_in, const int* in_sizes, int n_in,
                              void* d_out, int out_size)
{
    const float* inp = (const float*)d_in[0];   // [32,3,512,512]
    const float* wgt = (const float*)d_in[1];   // [3,1,13,13]
    float* out = (float*)d_out;                 // [32,3,128,128]

    dim3 grid(96, 128 / TH);                    // 96 images, 16 row-tiles
    aa_interp_kernel<<<grid, 256>>>(inp, wgt, out);
}